// round 1
// baseline (speedup 1.0000x reference)
#include <cuda_runtime.h>
#include <cuda_bf16.h>
#include <math_constants.h>

// Problem constants
#define BATCH 8
#define SEQ   2048
#define DIM   1024
#define NROWS (BATCH * SEQ)          // 16384

// Tiling
#define BM 128
#define BN 128
#define BK 16
#define TM 8
#define TN 8
#define NTHREADS 256

// Scratch (static device globals — allocation inside kernel_launch is forbidden)
__device__ float g_Q[(size_t)NROWS * DIM];            // 64 MB
__device__ float g_K[(size_t)NROWS * DIM];            // 64 MB
__device__ float g_V[(size_t)NROWS * DIM];            // 64 MB
__device__ float g_S[(size_t)BATCH * SEQ * SEQ];      // 128 MB

// ---------------------------------------------------------------------------
// NT GEMM: C[m,n] = scale * dot(A[m,:], B[n,:]) + bias[n]
// A: [M,K] row-major, B: [N,K] row-major. Optional batch via blockIdx.z.
// ---------------------------------------------------------------------------
__global__ __launch_bounds__(NTHREADS)
void gemm_nt(const float* __restrict__ A, const float* __restrict__ B,
             const float* __restrict__ bias, float* __restrict__ C,
             int M, int N, int K, float scale,
             long sA, long sB, long sC)
{
    A += (long)blockIdx.z * sA;
    B += (long)blockIdx.z * sB;
    C += (long)blockIdx.z * sC;

    __shared__ float As[BK][BM];
    __shared__ float Bs[BK][BN];

    const int tid = threadIdx.x;
    const int m0 = blockIdx.y * BM;
    const int n0 = blockIdx.x * BN;
    const int tx = tid & 15;       // 0..15 -> cols
    const int ty = tid >> 4;       // 0..15 -> rows

    float acc[TM][TN];
#pragma unroll
    for (int i = 0; i < TM; i++)
#pragma unroll
        for (int j = 0; j < TN; j++) acc[i][j] = 0.f;

    for (int k0 = 0; k0 < K; k0 += BK) {
        // Load A tile (BM x BK) transposed into As[k][m]. 512 float4 / 256 thr.
#pragma unroll
        for (int i = 0; i < 2; i++) {
            int f  = tid * 2 + i;          // 0..511
            int r  = f >> 2;               // row 0..127
            int kc = (f & 3) * 4;          // k sub-col 0,4,8,12
            float4 v = *reinterpret_cast<const float4*>(A + (long)(m0 + r) * K + k0 + kc);
            As[kc + 0][r] = v.x; As[kc + 1][r] = v.y;
            As[kc + 2][r] = v.z; As[kc + 3][r] = v.w;
        }
        // Load B tile (BN x BK) transposed into Bs[k][n]
#pragma unroll
        for (int i = 0; i < 2; i++) {
            int f  = tid * 2 + i;
            int r  = f >> 2;
            int kc = (f & 3) * 4;
            float4 v = *reinterpret_cast<const float4*>(B + (long)(n0 + r) * K + k0 + kc);
            Bs[kc + 0][r] = v.x; Bs[kc + 1][r] = v.y;
            Bs[kc + 2][r] = v.z; Bs[kc + 3][r] = v.w;
        }
        __syncthreads();

#pragma unroll
        for (int kk = 0; kk < BK; kk++) {
            float ar[TM], br[TN];
            *reinterpret_cast<float4*>(ar)     = *reinterpret_cast<const float4*>(&As[kk][ty * TM]);
            *reinterpret_cast<float4*>(ar + 4) = *reinterpret_cast<const float4*>(&As[kk][ty * TM + 4]);
            *reinterpret_cast<float4*>(br)     = *reinterpret_cast<const float4*>(&Bs[kk][tx * TN]);
            *reinterpret_cast<float4*>(br + 4) = *reinterpret_cast<const float4*>(&Bs[kk][tx * TN + 4]);
#pragma unroll
            for (int i = 0; i < TM; i++)
#pragma unroll
                for (int j = 0; j < TN; j++)
                    acc[i][j] = fmaf(ar[i], br[j], acc[i][j]);
        }
        __syncthreads();
    }

#pragma unroll
    for (int i = 0; i < TM; i++) {
        long row = m0 + ty * TM + i;
#pragma unroll
        for (int j = 0; j < TN; j += 4) {
            int n = n0 + tx * TN + j;
            float4 o;
            o.x = acc[i][j + 0] * scale;
            o.y = acc[i][j + 1] * scale;
            o.z = acc[i][j + 2] * scale;
            o.w = acc[i][j + 3] * scale;
            if (bias) {
                o.x += bias[n + 0]; o.y += bias[n + 1];
                o.z += bias[n + 2]; o.w += bias[n + 3];
            }
            *reinterpret_cast<float4*>(C + row * N + n) = o;
        }
    }
}

// ---------------------------------------------------------------------------
// NN GEMM: C[m,n] = sum_k A[m,k] * B[k,n]
// A: [M,K] row-major, B: [K,N] row-major. Batch via blockIdx.z.
// ---------------------------------------------------------------------------
__global__ __launch_bounds__(NTHREADS)
void gemm_nn(const float* __restrict__ A, const float* __restrict__ B,
             float* __restrict__ C,
             int M, int N, int K,
             long sA, long sB, long sC)
{
    A += (long)blockIdx.z * sA;
    B += (long)blockIdx.z * sB;
    C += (long)blockIdx.z * sC;

    __shared__ float As[BK][BM];
    __shared__ float Bs[BK][BN];

    const int tid = threadIdx.x;
    const int m0 = blockIdx.y * BM;
    const int n0 = blockIdx.x * BN;
    const int tx = tid & 15;
    const int ty = tid >> 4;

    float acc[TM][TN];
#pragma unroll
    for (int i = 0; i < TM; i++)
#pragma unroll
        for (int j = 0; j < TN; j++) acc[i][j] = 0.f;

    for (int k0 = 0; k0 < K; k0 += BK) {
        // A tile (BM x BK) transposed
#pragma unroll
        for (int i = 0; i < 2; i++) {
            int f  = tid * 2 + i;
            int r  = f >> 2;
            int kc = (f & 3) * 4;
            float4 v = *reinterpret_cast<const float4*>(A + (long)(m0 + r) * K + k0 + kc);
            As[kc + 0][r] = v.x; As[kc + 1][r] = v.y;
            As[kc + 2][r] = v.z; As[kc + 3][r] = v.w;
        }
        // B tile (BK x BN) direct: rows are k, cols contiguous n
#pragma unroll
        for (int i = 0; i < 2; i++) {
            int f  = tid * 2 + i;          // 0..511
            int r  = f >> 5;               // k row 0..15
            int nc = (f & 31) * 4;         // n col 0..124
            float4 v = *reinterpret_cast<const float4*>(B + (long)(k0 + r) * N + n0 + nc);
            *reinterpret_cast<float4*>(&Bs[r][nc]) = v;
        }
        __syncthreads();

#pragma unroll
        for (int kk = 0; kk < BK; kk++) {
            float ar[TM], br[TN];
            *reinterpret_cast<float4*>(ar)     = *reinterpret_cast<const float4*>(&As[kk][ty * TM]);
            *reinterpret_cast<float4*>(ar + 4) = *reinterpret_cast<const float4*>(&As[kk][ty * TM + 4]);
            *reinterpret_cast<float4*>(br)     = *reinterpret_cast<const float4*>(&Bs[kk][tx * TN]);
            *reinterpret_cast<float4*>(br + 4) = *reinterpret_cast<const float4*>(&Bs[kk][tx * TN + 4]);
#pragma unroll
            for (int i = 0; i < TM; i++)
#pragma unroll
                for (int j = 0; j < TN; j++)
                    acc[i][j] = fmaf(ar[i], br[j], acc[i][j]);
        }
        __syncthreads();
    }

#pragma unroll
    for (int i = 0; i < TM; i++) {
        long row = m0 + ty * TM + i;
#pragma unroll
        for (int j = 0; j < TN; j += 4) {
            int n = n0 + tx * TN + j;
            float4 o = make_float4(acc[i][j], acc[i][j + 1], acc[i][j + 2], acc[i][j + 3]);
            *reinterpret_cast<float4*>(C + row * N + n) = o;
        }
    }
}

// ---------------------------------------------------------------------------
// Row softmax over SEQ=2048 columns. One block (256 thr) per row, 8 vals/thr.
// ---------------------------------------------------------------------------
__global__ __launch_bounds__(256)
void softmax_rows(float* __restrict__ S)
{
    const long row = blockIdx.x;
    float* p = S + row * (long)SEQ;
    const int tid = threadIdx.x;

    float v[8];
    float m = -CUDART_INF_F;
#pragma unroll
    for (int i = 0; i < 8; i++) {
        v[i] = p[tid + i * 256];
        m = fmaxf(m, v[i]);
    }
#pragma unroll
    for (int o = 16; o > 0; o >>= 1) m = fmaxf(m, __shfl_xor_sync(0xFFFFFFFFu, m, o));

    __shared__ float smax[8];
    __shared__ float ssum[8];
    if ((tid & 31) == 0) smax[tid >> 5] = m;
    __syncthreads();
    float mm = smax[0];
#pragma unroll
    for (int i = 1; i < 8; i++) mm = fmaxf(mm, smax[i]);

    float s = 0.f;
#pragma unroll
    for (int i = 0; i < 8; i++) {
        v[i] = __expf(v[i] - mm);
        s += v[i];
    }
#pragma unroll
    for (int o = 16; o > 0; o >>= 1) s += __shfl_xor_sync(0xFFFFFFFFu, s, o);
    if ((tid & 31) == 0) ssum[tid >> 5] = s;
    __syncthreads();
    float tot = 0.f;
#pragma unroll
    for (int i = 0; i < 8; i++) tot += ssum[i];

    float inv = 1.f / tot;
#pragma unroll
    for (int i = 0; i < 8; i++) p[tid + i * 256] = v[i] * inv;
}

// ---------------------------------------------------------------------------
extern "C" void kernel_launch(void* const* d_in, const int* in_sizes, int n_in,
                              void* d_out, int out_size)
{
    const float* X  = (const float*)d_in[0];
    const float* Wq = (const float*)d_in[1];
    const float* bq = (const float*)d_in[2];
    const float* Wk = (const float*)d_in[3];
    const float* bk = (const float*)d_in[4];
    const float* Wv = (const float*)d_in[5];
    const float* bv = (const float*)d_in[6];
    float* O = (float*)d_out;

    float *Q, *K, *V, *S;
    cudaGetSymbolAddress((void**)&Q, g_Q);
    cudaGetSymbolAddress((void**)&K, g_K);
    cudaGetSymbolAddress((void**)&V, g_V);
    cudaGetSymbolAddress((void**)&S, g_S);

    dim3 blk(NTHREADS);

    // QKV projections: [16384,1024] = X[16384,1024] @ W^T + b
    dim3 gq(DIM / BN, NROWS / BM, 1);                       // (8, 128)
    gemm_nt<<<gq, blk>>>(X, Wq, bq, Q, NROWS, DIM, DIM, 1.f, 0, 0, 0);
    gemm_nt<<<gq, blk>>>(X, Wk, bk, K, NROWS, DIM, DIM, 1.f, 0, 0, 0);
    gemm_nt<<<gq, blk>>>(X, Wv, bv, V, NROWS, DIM, DIM, 1.f, 0, 0, 0);

    // scores: per batch, S = (Q @ K^T) / 32
    dim3 gs(SEQ / BN, SEQ / BM, BATCH);                     // (16, 16, 8)
    gemm_nt<<<gs, blk>>>(Q, K, nullptr, S, SEQ, SEQ, DIM, 0.03125f,
                         (long)SEQ * DIM, (long)SEQ * DIM, (long)SEQ * SEQ);

    // softmax rows (in place)
    softmax_rows<<<NROWS, 256>>>(S);

    // O = P @ V (per batch, NN)
    dim3 gp(DIM / BN, SEQ / BM, BATCH);                     // (8, 16, 8)
    gemm_nn<<<gp, blk>>>(S, V, O, SEQ, DIM, SEQ,
                         (long)SEQ * SEQ, (long)SEQ * DIM, (long)SEQ * DIM);
}

// round 3
// speedup vs baseline: 2.0830x; 2.0830x over previous
#include <cuda_runtime.h>
#include <cuda_bf16.h>
#include <math_constants.h>
#include <cstdint>

#define BATCH 8
#define SEQ   2048
#define DIM   1024
#define NROWS (BATCH*SEQ)

typedef __nv_bfloat16 bf16;

// ---------------------------------------------------------------------------
// Scratch (static device globals; allocation in kernel_launch is forbidden)
// ---------------------------------------------------------------------------
__device__ bf16  g_Xhi[(size_t)NROWS*DIM];
__device__ bf16  g_Xlo[(size_t)NROWS*DIM];
__device__ bf16  g_Whi[3][(size_t)DIM*DIM];
__device__ bf16  g_Wlo[3][(size_t)DIM*DIM];
__device__ bf16  g_Qhi[(size_t)NROWS*DIM];
__device__ bf16  g_Qlo[(size_t)NROWS*DIM];
__device__ bf16  g_Khi[(size_t)NROWS*DIM];
__device__ bf16  g_Klo[(size_t)NROWS*DIM];
__device__ float g_Vf [(size_t)NROWS*DIM];
__device__ bf16  g_Vthi[(size_t)BATCH*DIM*SEQ];
__device__ bf16  g_Vtlo[(size_t)BATCH*DIM*SEQ];
__device__ float g_S  [(size_t)BATCH*SEQ*SEQ];
__device__ bf16  g_Phi[(size_t)BATCH*SEQ*SEQ];
__device__ bf16  g_Plo[(size_t)BATCH*SEQ*SEQ];

// ---------------------------------------------------------------------------
// PTX helpers (sm_80+ architecture-agnostic: mma.sync / ldmatrix / cp.async)
// ---------------------------------------------------------------------------
__device__ __forceinline__ uint32_t smem_u32(const void* p) {
    return (uint32_t)__cvta_generic_to_shared(p);
}
__device__ __forceinline__ void cpasync16(uint32_t s, const void* g) {
    asm volatile("cp.async.cg.shared.global [%0], [%1], 16;" :: "r"(s), "l"(g));
}
__device__ __forceinline__ void cp_commit() {
    asm volatile("cp.async.commit_group;" ::: "memory");
}
template<int N> __device__ __forceinline__ void cp_wait() {
    asm volatile("cp.async.wait_group %0;" :: "n"(N) : "memory");
}
__device__ __forceinline__ void ldsm4(uint32_t* r, uint32_t addr) {
    asm volatile("ldmatrix.sync.aligned.m8n8.x4.shared.b16 {%0,%1,%2,%3}, [%4];"
                 : "=r"(r[0]), "=r"(r[1]), "=r"(r[2]), "=r"(r[3]) : "r"(addr));
}
__device__ __forceinline__ void mma16816(float* c, const uint32_t* a, uint32_t b0, uint32_t b1) {
    asm volatile("mma.sync.aligned.m16n8k16.row.col.f32.bf16.bf16.f32 "
                 "{%0,%1,%2,%3}, {%4,%5,%6,%7}, {%8,%9}, {%0,%1,%2,%3};"
                 : "+f"(c[0]), "+f"(c[1]), "+f"(c[2]), "+f"(c[3])
                 : "r"(a[0]), "r"(a[1]), "r"(a[2]), "r"(a[3]), "r"(b0), "r"(b1));
}
__device__ __forceinline__ void split2(float v, bf16& h, bf16& l) {
    h = __float2bfloat16(v);
    l = __float2bfloat16(v - __bfloat162float(h));
}

// ---------------------------------------------------------------------------
// NT GEMM via mma.sync bf16, 128x128x32 tile, cp.async double buffer.
// 3 accumulation passes into fp32 register accumulators:
//   C = Ahi*Bhi + Ahi*Blo + Alo*Bhi
// A: [M,K] row-major (hi/lo), B: [N,K] row-major (hi/lo). Batch via blockIdx.z.
// Output: fp32 (Cf) or split bf16 (Chi/Clo). Optional bias + scale.
// ---------------------------------------------------------------------------
#define BM 128
#define BN 128
#define BKC 32
#define LDS_PAD 8
#define LDA (BKC + LDS_PAD)   // 40 bf16 = 80 bytes per smem row
#define GT 256

__global__ void __launch_bounds__(GT)
gemm_mma(const bf16* __restrict__ Ahi, const bf16* __restrict__ Alo,
         const bf16* __restrict__ Bhi, const bf16* __restrict__ Blo,
         const float* __restrict__ bias,
         float* __restrict__ Cf, bf16* __restrict__ Chi, bf16* __restrict__ Clo,
         int N, int K, float scale,
         long sA, long sB, long sC)
{
    __shared__ bf16 sAt[2][BM * LDA];
    __shared__ bf16 sBt[2][BN * LDA];

    const int tid = threadIdx.x;
    const int wid = tid >> 5, lid = tid & 31;
    const long z = blockIdx.z;
    Ahi += z * sA; Alo += z * sA;
    Bhi += z * sB; Blo += z * sB;
    if (Cf)  Cf  += z * sC;
    if (Chi) { Chi += z * sC; Clo += z * sC; }
    const int m0 = blockIdx.y * BM;
    const int n0 = blockIdx.x * BN;

    // warp tile: 32 (m) x 64 (n); warps laid out 4 (m) x 2 (n)
    const int wm = (wid & 3) * 32;
    const int wn = (wid >> 2) * 64;

    float acc[2][8][4];
#pragma unroll
    for (int i = 0; i < 2; i++)
#pragma unroll
        for (int j = 0; j < 8; j++)
#pragma unroll
            for (int t = 0; t < 4; t++) acc[i][j][t] = 0.f;

    const int kchunks = K / BKC;
    const int it_total = 3 * kchunks;

    // per-thread cp.async slots: seg = i*256 + tid; row = seg/4, segcol = seg%4
    const int ld_r0 = tid >> 2,  ld_c = (tid & 3) * 8;
    const int ld_r1 = ld_r0 + 64;

    // ldmatrix per-thread base offsets (bytes)
    const uint32_t lm_row = lid & 15;           // row within 16-row tile
    const uint32_t lm_sel = (lid >> 4) * 8;     // k sub-block 0/8

    auto issue_loads = [&](int it, int buf) {
        const int pass = it / kchunks;
        const int kc   = it - pass * kchunks;
        const bf16* Ap = (pass == 2) ? Alo : Ahi;
        const bf16* Bp = (pass == 1) ? Blo : Bhi;
        const bf16* Ag = Ap + (long)m0 * K + kc * BKC;
        const bf16* Bg = Bp + (long)n0 * K + kc * BKC;
        uint32_t aS = smem_u32(&sAt[buf][0]);
        uint32_t bS = smem_u32(&sBt[buf][0]);
        cpasync16(aS + (ld_r0 * LDA + ld_c) * 2, Ag + (long)ld_r0 * K + ld_c);
        cpasync16(aS + (ld_r1 * LDA + ld_c) * 2, Ag + (long)ld_r1 * K + ld_c);
        cpasync16(bS + (ld_r0 * LDA + ld_c) * 2, Bg + (long)ld_r0 * K + ld_c);
        cpasync16(bS + (ld_r1 * LDA + ld_c) * 2, Bg + (long)ld_r1 * K + ld_c);
        cp_commit();
    };

    issue_loads(0, 0);

    for (int it = 0; it < it_total; ++it) {
        const int buf = it & 1;
        if (it + 1 < it_total) {
            issue_loads(it + 1, buf ^ 1);
            cp_wait<1>();
        } else {
            cp_wait<0>();
        }
        __syncthreads();

        const uint32_t aBase = smem_u32(&sAt[buf][0]) + ((wm + lm_row) * LDA + lm_sel) * 2;
        const uint32_t bBase = smem_u32(&sBt[buf][0]) + ((wn + lm_row) * LDA + lm_sel) * 2;

#pragma unroll
        for (int kk = 0; kk < BKC; kk += 16) {
            uint32_t af[2][4];
#pragma unroll
            for (int i = 0; i < 2; i++)
                ldsm4(af[i], aBase + (i * 16 * LDA + kk) * 2);
            uint32_t bfr[4][4];
#pragma unroll
            for (int j = 0; j < 4; j++)
                ldsm4(bfr[j], bBase + (j * 16 * LDA + kk) * 2);
#pragma unroll
            for (int i = 0; i < 2; i++)
#pragma unroll
                for (int j = 0; j < 4; j++) {
                    mma16816(acc[i][2*j],   af[i], bfr[j][0], bfr[j][2]);
                    mma16816(acc[i][2*j+1], af[i], bfr[j][1], bfr[j][3]);
                }
        }
        __syncthreads();
    }

    // Epilogue. C fragment m16n8: c0=C[g][tg*2], c1=C[g][tg*2+1], c2/c3 at row g+8.
    const int g = lid >> 2, tg = lid & 3;
#pragma unroll
    for (int i = 0; i < 2; i++) {
        const long r0 = m0 + wm + i * 16 + g;
        const long r1 = r0 + 8;
#pragma unroll
        for (int j = 0; j < 8; j++) {
            const int col = n0 + wn + j * 8 + tg * 2;
            float c0 = acc[i][j][0] * scale;
            float c1 = acc[i][j][1] * scale;
            float c2 = acc[i][j][2] * scale;
            float c3 = acc[i][j][3] * scale;
            if (bias) {
                const float b0 = __ldg(&bias[col]), b1 = __ldg(&bias[col + 1]);
                c0 += b0; c1 += b1; c2 += b0; c3 += b1;
            }
            if (Chi) {
                bf16 h0, l0, h1, l1, h2, l2, h3, l3;
                split2(c0, h0, l0); split2(c1, h1, l1);
                split2(c2, h2, l2); split2(c3, h3, l3);
                *(__nv_bfloat162*)(Chi + r0 * N + col) = __nv_bfloat162(h0, h1);
                *(__nv_bfloat162*)(Clo + r0 * N + col) = __nv_bfloat162(l0, l1);
                *(__nv_bfloat162*)(Chi + r1 * N + col) = __nv_bfloat162(h2, h3);
                *(__nv_bfloat162*)(Clo + r1 * N + col) = __nv_bfloat162(l2, l3);
            } else {
                *(float2*)(Cf + r0 * N + col) = make_float2(c0, c1);
                *(float2*)(Cf + r1 * N + col) = make_float2(c2, c3);
            }
        }
    }
}

// ---------------------------------------------------------------------------
// fp32 -> (bf16 hi, bf16 lo) elementwise split
// ---------------------------------------------------------------------------
__global__ void __launch_bounds__(256)
split_kernel(const float* __restrict__ x, bf16* __restrict__ h, bf16* __restrict__ l, long n)
{
    long i = ((long)blockIdx.x * 256 + threadIdx.x) * 4;
    if (i >= n) return;
    float4 v = *(const float4*)(x + i);
    bf16 hb[4], lb[4];
    split2(v.x, hb[0], lb[0]);
    split2(v.y, hb[1], lb[1]);
    split2(v.z, hb[2], lb[2]);
    split2(v.w, hb[3], lb[3]);
    *(uint2*)(h + i) = *(uint2*)hb;
    *(uint2*)(l + i) = *(uint2*)lb;
}

// ---------------------------------------------------------------------------
// Transpose V [B,S,D] fp32 -> Vt [B,D,S] split bf16
// ---------------------------------------------------------------------------
__global__ void __launch_bounds__(256)
transpose_split(const float* __restrict__ V, bf16* __restrict__ th, bf16* __restrict__ tl)
{
    __shared__ float t[32][33];
    const int z  = blockIdx.z;
    const int d0 = blockIdx.x * 32;
    const int s0 = blockIdx.y * 32;
    const int tx = threadIdx.x & 31;
    const int ty = threadIdx.x >> 5;      // 0..7
#pragma unroll
    for (int i = 0; i < 4; i++) {
        int s = s0 + ty + i * 8;
        t[ty + i * 8][tx] = V[((long)z * SEQ + s) * DIM + d0 + tx];
    }
    __syncthreads();
#pragma unroll
    for (int i = 0; i < 4; i++) {
        int d = d0 + ty + i * 8;
        float v = t[tx][ty + i * 8];
        bf16 h, l;
        split2(v, h, l);
        long idx = ((long)z * DIM + d) * SEQ + s0 + tx;
        th[idx] = h;
        tl[idx] = l;
    }
}

// ---------------------------------------------------------------------------
// Row softmax over SEQ cols + split-bf16 output
// ---------------------------------------------------------------------------
__global__ void __launch_bounds__(256)
softmax_split(const float* __restrict__ S, bf16* __restrict__ Ph, bf16* __restrict__ Pl)
{
    const long row = blockIdx.x;
    const float* p = S + row * (long)SEQ;
    const int tid = threadIdx.x;

    float v[8];
    float m = -CUDART_INF_F;
#pragma unroll
    for (int i = 0; i < 8; i++) {
        v[i] = p[tid + i * 256];
        m = fmaxf(m, v[i]);
    }
#pragma unroll
    for (int o = 16; o > 0; o >>= 1) m = fmaxf(m, __shfl_xor_sync(0xFFFFFFFFu, m, o));

    __shared__ float smax[8], ssum[8];
    if ((tid & 31) == 0) smax[tid >> 5] = m;
    __syncthreads();
    float mm = smax[0];
#pragma unroll
    for (int i = 1; i < 8; i++) mm = fmaxf(mm, smax[i]);

    float s = 0.f;
#pragma unroll
    for (int i = 0; i < 8; i++) { v[i] = __expf(v[i] - mm); s += v[i]; }
#pragma unroll
    for (int o = 16; o > 0; o >>= 1) s += __shfl_xor_sync(0xFFFFFFFFu, s, o);
    if ((tid & 31) == 0) ssum[tid >> 5] = s;
    __syncthreads();
    float tot = 0.f;
#pragma unroll
    for (int i = 0; i < 8; i++) tot += ssum[i];

    const float inv = 1.f / tot;
#pragma unroll
    for (int i = 0; i < 8; i++) {
        float pv = v[i] * inv;
        bf16 h, l;
        split2(pv, h, l);
        long idx = row * (long)SEQ + tid + i * 256;
        Ph[idx] = h;
        Pl[idx] = l;
    }
}

// ---------------------------------------------------------------------------
extern "C" void kernel_launch(void* const* d_in, const int* in_sizes, int n_in,
                              void* d_out, int out_size)
{
    const float* X  = (const float*)d_in[0];
    const float* Wq = (const float*)d_in[1];
    const float* bq = (const float*)d_in[2];
    const float* Wk = (const float*)d_in[3];
    const float* bk = (const float*)d_in[4];
    const float* Wv = (const float*)d_in[5];
    const float* bv = (const float*)d_in[6];
    float* O = (float*)d_out;

    bf16 *Xhi, *Xlo, *Whi, *Wlo, *Qhi, *Qlo, *Khi, *Klo, *Vthi, *Vtlo, *Phi, *Plo;
    float *Vf, *S;
    cudaGetSymbolAddress((void**)&Xhi, g_Xhi);
    cudaGetSymbolAddress((void**)&Xlo, g_Xlo);
    cudaGetSymbolAddress((void**)&Whi, g_Whi);
    cudaGetSymbolAddress((void**)&Wlo, g_Wlo);
    cudaGetSymbolAddress((void**)&Qhi, g_Qhi);
    cudaGetSymbolAddress((void**)&Qlo, g_Qlo);
    cudaGetSymbolAddress((void**)&Khi, g_Khi);
    cudaGetSymbolAddress((void**)&Klo, g_Klo);
    cudaGetSymbolAddress((void**)&Vf,  g_Vf);
    cudaGetSymbolAddress((void**)&Vthi, g_Vthi);
    cudaGetSymbolAddress((void**)&Vtlo, g_Vtlo);
    cudaGetSymbolAddress((void**)&S,   g_S);
    cudaGetSymbolAddress((void**)&Phi, g_Phi);
    cudaGetSymbolAddress((void**)&Plo, g_Plo);

    const long nX = (long)NROWS * DIM;
    const long nW = (long)DIM * DIM;

    // Input splits
    split_kernel<<<(int)(nX / 4 / 256), 256>>>(X,  Xhi, Xlo, nX);
    split_kernel<<<(int)(nW / 4 / 256), 256>>>(Wq, Whi + 0 * nW, Wlo + 0 * nW, nW);
    split_kernel<<<(int)(nW / 4 / 256), 256>>>(Wk, Whi + 1 * nW, Wlo + 1 * nW, nW);
    split_kernel<<<(int)(nW / 4 / 256), 256>>>(Wv, Whi + 2 * nW, Wlo + 2 * nW, nW);

    // QKV projections: [16384,1024] = X @ W^T + b (NT; split-bf16 out for Q,K; fp32 for V)
    dim3 gp(DIM / BN, NROWS / BM, 1);
    gemm_mma<<<gp, GT>>>(Xhi, Xlo, Whi + 0 * nW, Wlo + 0 * nW, bq,
                         nullptr, Qhi, Qlo, DIM, DIM, 1.f, 0, 0, 0);
    gemm_mma<<<gp, GT>>>(Xhi, Xlo, Whi + 1 * nW, Wlo + 1 * nW, bk,
                         nullptr, Khi, Klo, DIM, DIM, 1.f, 0, 0, 0);
    gemm_mma<<<gp, GT>>>(Xhi, Xlo, Whi + 2 * nW, Wlo + 2 * nW, bv,
                         Vf, nullptr, nullptr, DIM, DIM, 1.f, 0, 0, 0);

    // V transpose + split: [B,S,D] -> [B,D,S]
    transpose_split<<<dim3(DIM / 32, SEQ / 32, BATCH), 256>>>(Vf, Vthi, Vtlo);

    // Scores: S = (Q @ K^T) / 32 (NT, per batch)
    dim3 gs(SEQ / BN, SEQ / BM, BATCH);
    gemm_mma<<<gs, GT>>>(Qhi, Qlo, Khi, Klo, nullptr,
                         S, nullptr, nullptr, SEQ, DIM, 0.03125f,
                         (long)SEQ * DIM, (long)SEQ * DIM, (long)SEQ * SEQ);

    // Softmax + split P
    softmax_split<<<NROWS, 256>>>(S, Phi, Plo);

    // O = P @ Vt^T (NT, per batch)
    dim3 gv(DIM / BN, SEQ / BM, BATCH);
    gemm_mma<<<gv, GT>>>(Phi, Plo, Vthi, Vtlo, nullptr,
                         O, nullptr, nullptr, DIM, SEQ, 1.f,
                         (long)SEQ * SEQ, (long)DIM * SEQ, (long)SEQ * DIM);
}